// round 6
// baseline (speedup 1.0000x reference)
#include <cuda_runtime.h>
#include <stdint.h>

// Instant-NGP multiresolution hash-grid encode, spatially-sorted gather.
// x: [N,3] fp32, tables: [16, 2^19, 2] fp32 -> out: [N, 32] fp32.
//
// Pipeline (one graph, 5 kernels):
//   1. zero 64^3 histogram
//   2. histogram of points by spatial cell
//   3. exclusive scan (single block)
//   4. scatter -> g_perm (points grouped by cell)
//   5. encode: warp = 4 sorted points x 8 level-pairs; thread does 2 levels,
//      stores one float4. Sorted neighbors share corner cache lines at
//      coarse/mid levels -> gather wavefronts coalesce across the 4 points.
//      Even-ix corners pair into one aligned float4 (hash x-prime = 1).

#define NGP_LEVELS 16
#define NGP_T      524288u          // 2^19
#define NGP_TMASK  (NGP_T - 1u)
#define NGP_P1     2654435761u
#define NGP_P2     805459861u

#define NB   64                     // sort grid per axis
#define NB3  (NB*NB*NB)             // 262144 buckets
#define CAPP (1u<<21)               // max points supported (2M, problem uses 1M)

__device__ unsigned int g_hist[NB3];
__device__ unsigned int g_offs[NB3];
__device__ unsigned int g_perm[CAPP];

__device__ float g_res[NGP_LEVELS] = {
    16.f, 24.f, 36.f, 54.f, 81.f, 121.f, 182.f, 273.f,
    410.f, 615.f, 922.f, 1383.f, 2075.f, 3113.f, 4670.f, 7006.f
};

// ---------------- sort kernels ----------------

__global__ void zero_hist_kernel()
{
    int i = blockIdx.x * blockDim.x + threadIdx.x;
    if (i < NB3) g_hist[i] = 0u;
}

__device__ __forceinline__ unsigned int cell_of(float px, float py, float pz)
{
    unsigned cx = (unsigned)fminf(fmaxf(px * (float)NB, 0.f), (float)(NB - 1));
    unsigned cy = (unsigned)fminf(fmaxf(py * (float)NB, 0.f), (float)(NB - 1));
    unsigned cz = (unsigned)fminf(fmaxf(pz * (float)NB, 0.f), (float)(NB - 1));
    return (cz * NB + cy) * NB + cx;
}

__global__ void hist_kernel(const float* __restrict__ x, int npts)
{
    int i = blockIdx.x * blockDim.x + threadIdx.x;
    if (i >= npts) return;
    const float* xp = x + (size_t)i * 3;
    atomicAdd(&g_hist[cell_of(xp[0], xp[1], xp[2])], 1u);
}

__global__ void scan_kernel()
{
    __shared__ unsigned int sm[1024];
    int tid = threadIdx.x;
    const int C = NB3 / 1024;           // buckets per thread
    unsigned base = tid * C;

    unsigned s = 0;
    for (int i = 0; i < C; i++) s += g_hist[base + i];
    sm[tid] = s;
    __syncthreads();

    // Hillis-Steele inclusive scan over 1024 partials
    for (int off = 1; off < 1024; off <<= 1) {
        unsigned v = (tid >= off) ? sm[tid - off] : 0u;
        __syncthreads();
        sm[tid] += v;
        __syncthreads();
    }

    unsigned run = (tid > 0) ? sm[tid - 1] : 0u;
    for (int i = 0; i < C; i++) {
        g_offs[base + i] = run;
        run += g_hist[base + i];
    }
}

__global__ void scatter_kernel(const float* __restrict__ x, int npts)
{
    int i = blockIdx.x * blockDim.x + threadIdx.x;
    if (i >= npts) return;
    const float* xp = x + (size_t)i * 3;
    unsigned cell = cell_of(xp[0], xp[1], xp[2]);
    unsigned pos = atomicAdd(&g_offs[cell], 1u);
    if (pos < CAPP) g_perm[pos] = (unsigned)i;
}

// ---------------- encode kernel ----------------

// one level's encode for one point; returns float2 feature
__device__ __forceinline__ float2 encode_level(
    const float2* __restrict__ tbl,
    float px, float py, float pz, float res)
{
    float sx = px * res, sy = py * res, sz = pz * res;
    float fx_ = floorf(sx), fy_ = floorf(sy), fz_ = floorf(sz);
    float gx = sx - fx_, gy = sy - fy_, gz = sz - fz_;
    uint32_t ix = (uint32_t)fx_, iy = (uint32_t)fy_, iz = (uint32_t)fz_;

    uint32_t hy0 = iy * NGP_P1;
    uint32_t hy1 = hy0 + NGP_P1;
    uint32_t hz0 = iz * NGP_P2;
    uint32_t hz1 = hz0 + NGP_P2;

    uint32_t m00 = hy0 ^ hz0;
    uint32_t m01 = hy0 ^ hz1;
    uint32_t m10 = hy1 ^ hz0;
    uint32_t m11 = hy1 ^ hz1;

    float wx0 = 1.f - gx, wx1 = gx;
    float wy0 = 1.f - gy, wy1 = gy;
    float wz0 = 1.f - gz, wz1 = gz;

    float w00 = wy0 * wz0;
    float w01 = wy0 * wz1;
    float w10 = wy1 * wz0;
    float w11 = wy1 * wz1;

    float ax = 0.f, ay = 0.f;

    if ((ix & 1u) == 0u) {
        // even ix: corners (ix,jk) and (ix+1,jk) sit at idx, idx^1 -> one float4
        uint32_t a00 = (ix ^ m00) & NGP_TMASK;
        uint32_t a01 = (ix ^ m01) & NGP_TMASK;
        uint32_t a10 = (ix ^ m10) & NGP_TMASK;
        uint32_t a11 = (ix ^ m11) & NGP_TMASK;

        const float4* t4 = (const float4*)tbl;
        float4 q00 = __ldg(t4 + (a00 >> 1));
        float4 q01 = __ldg(t4 + (a01 >> 1));
        float4 q10 = __ldg(t4 + (a10 >> 1));
        float4 q11 = __ldg(t4 + (a11 >> 1));

        // q.lo = even table index. If a&1==0, corner ix is lo (weight wx0),
        // else corner ix is hi. Select weights, not features.
        float wl00 = (a00 & 1u) ? wx1 : wx0;  float wh00 = (a00 & 1u) ? wx0 : wx1;
        float wl01 = (a01 & 1u) ? wx1 : wx0;  float wh01 = (a01 & 1u) ? wx0 : wx1;
        float wl10 = (a10 & 1u) ? wx1 : wx0;  float wh10 = (a10 & 1u) ? wx0 : wx1;
        float wl11 = (a11 & 1u) ? wx1 : wx0;  float wh11 = (a11 & 1u) ? wx0 : wx1;

        ax = fmaf(w00, fmaf(wl00, q00.x, wh00 * q00.z), ax);
        ay = fmaf(w00, fmaf(wl00, q00.y, wh00 * q00.w), ay);
        ax = fmaf(w01, fmaf(wl01, q01.x, wh01 * q01.z), ax);
        ay = fmaf(w01, fmaf(wl01, q01.y, wh01 * q01.w), ay);
        ax = fmaf(w10, fmaf(wl10, q10.x, wh10 * q10.z), ax);
        ay = fmaf(w10, fmaf(wl10, q10.y, wh10 * q10.w), ay);
        ax = fmaf(w11, fmaf(wl11, q11.x, wh11 * q11.z), ax);
        ay = fmaf(w11, fmaf(wl11, q11.y, wh11 * q11.w), ay);
    } else {
        // odd ix: 8 independent gathers
        uint32_t ix1 = ix + 1u;
        uint32_t a0 = (ix  ^ m00) & NGP_TMASK;
        uint32_t a1 = (ix  ^ m01) & NGP_TMASK;
        uint32_t a2 = (ix  ^ m10) & NGP_TMASK;
        uint32_t a3 = (ix  ^ m11) & NGP_TMASK;
        uint32_t a4 = (ix1 ^ m00) & NGP_TMASK;
        uint32_t a5 = (ix1 ^ m01) & NGP_TMASK;
        uint32_t a6 = (ix1 ^ m10) & NGP_TMASK;
        uint32_t a7 = (ix1 ^ m11) & NGP_TMASK;

        float2 fA00 = __ldg(tbl + a0);
        float2 fA01 = __ldg(tbl + a1);
        float2 fA10 = __ldg(tbl + a2);
        float2 fA11 = __ldg(tbl + a3);
        float2 fB00 = __ldg(tbl + a4);
        float2 fB01 = __ldg(tbl + a5);
        float2 fB10 = __ldg(tbl + a6);
        float2 fB11 = __ldg(tbl + a7);

        ax = fmaf(w00, fmaf(wx0, fA00.x, wx1 * fB00.x), ax);
        ay = fmaf(w00, fmaf(wx0, fA00.y, wx1 * fB00.y), ay);
        ax = fmaf(w01, fmaf(wx0, fA01.x, wx1 * fB01.x), ax);
        ay = fmaf(w01, fmaf(wx0, fA01.y, wx1 * fB01.y), ay);
        ax = fmaf(w10, fmaf(wx0, fA10.x, wx1 * fB10.x), ax);
        ay = fmaf(w10, fmaf(wx0, fA10.y, wx1 * fB10.y), ay);
        ax = fmaf(w11, fmaf(wx0, fA11.x, wx1 * fB11.x), ax);
        ay = fmaf(w11, fmaf(wx0, fA11.y, wx1 * fB11.y), ay);
    }
    return make_float2(ax, ay);
}

__global__ __launch_bounds__(256)
void ngp_encode_sorted_kernel(const float* __restrict__ x,
                              const float* __restrict__ tables,
                              float* __restrict__ out,
                              int npts)
{
    // warp = 4 sorted points x 8 level-pairs; thread -> (point slot, level pair)
    int slot  = threadIdx.x >> 3;           // 0..31 within block
    int lpair = threadIdx.x & 7;            // levels 2*lpair, 2*lpair+1
    int sp = blockIdx.x * 32 + slot;        // sorted position
    if (sp >= npts) return;

    int point = (int)g_perm[sp];

    const float* xp = x + (size_t)point * 3;
    float px = __ldg(xp + 0);
    float py = __ldg(xp + 1);
    float pz = __ldg(xp + 2);

    int l0 = lpair * 2;
    float res0 = __ldg(g_res + l0);
    float res1 = __ldg(g_res + l0 + 1);

    const float2* tbl0 = (const float2*)tables + (size_t)l0 * NGP_T;
    const float2* tbl1 = tbl0 + NGP_T;

    float2 r0 = encode_level(tbl0, px, py, pz, res0);
    float2 r1 = encode_level(tbl1, px, py, pz, res1);

    // out[point][levels 2*lpair .. 2*lpair+1] = one aligned float4
    float4* op = (float4*)out + (size_t)point * 8 + lpair;
    *op = make_float4(r0.x, r0.y, r1.x, r1.y);
}

// ---------------- launch ----------------

extern "C" void kernel_launch(void* const* d_in, const int* in_sizes, int n_in,
                              void* d_out, int out_size)
{
    const float* x      = (const float*)d_in[0];   // [N,3]
    const float* tables = (const float*)d_in[1];   // [16, 2^19, 2]
    float* out          = (float*)d_out;           // [N,32]

    int npts = in_sizes[0] / 3;

    // 1. zero histogram
    zero_hist_kernel<<<(NB3 + 255) / 256, 256>>>();
    // 2. histogram
    hist_kernel<<<(npts + 255) / 256, 256>>>(x, npts);
    // 3. scan
    scan_kernel<<<1, 1024>>>();
    // 4. scatter -> perm
    scatter_kernel<<<(npts + 255) / 256, 256>>>(x, npts);
    // 5. encode
    int nblocks = (npts + 31) / 32;
    ngp_encode_sorted_kernel<<<nblocks, 256>>>(x, tables, out, npts);
}

// round 7
// speedup vs baseline: 2.8979x; 2.8979x over previous
#include <cuda_runtime.h>
#include <stdint.h>

// Instant-NGP hash-grid encode with spatial bucketing.
// Pipeline: zero-hist -> hist -> scan(3 kernels, full chip) -> scatter -> encode.
// Encode: warp = 4 sorted points x 8 levels (thread = 1 level, same shape as
// the proven 324us kernel); sorted neighbors share corner cache lines at
// coarse levels. Even-ix corner pairs load as one aligned float4.

#define NGP_LEVELS 16
#define NGP_T      524288u
#define NGP_TMASK  (NGP_T - 1u)
#define NGP_P1     2654435761u
#define NGP_P2     805459861u

#define NB   64
#define NB3  (NB*NB*NB)            // 262144 buckets
#define NCHUNK 1024                 // scan chunks
#define CPER  (NB3/NCHUNK)          // 256 buckets per chunk
#define CAPP (1u<<21)

__device__ unsigned int g_hist[NB3];
__device__ unsigned int g_offs[NB3];
__device__ unsigned int g_part[NCHUNK];
__device__ unsigned int g_pexc[NCHUNK];
__device__ float4       g_pts[CAPP];     // sorted (x,y,z,bitcast(point))

__device__ float g_res[NGP_LEVELS] = {
    16.f, 24.f, 36.f, 54.f, 81.f, 121.f, 182.f, 273.f,
    410.f, 615.f, 922.f, 1383.f, 2075.f, 3113.f, 4670.f, 7006.f
};

// ---------------- sort kernels ----------------

__global__ void zero_hist_kernel()
{
    int i = blockIdx.x * blockDim.x + threadIdx.x;
    if (i < NB3) g_hist[i] = 0u;
}

__device__ __forceinline__ unsigned int cell_of(float px, float py, float pz)
{
    unsigned cx = (unsigned)fminf(fmaxf(px * (float)NB, 0.f), (float)(NB - 1));
    unsigned cy = (unsigned)fminf(fmaxf(py * (float)NB, 0.f), (float)(NB - 1));
    unsigned cz = (unsigned)fminf(fmaxf(pz * (float)NB, 0.f), (float)(NB - 1));
    return (cz * NB + cy) * NB + cx;
}

__global__ void hist_kernel(const float* __restrict__ x, int npts)
{
    int i = blockIdx.x * blockDim.x + threadIdx.x;
    if (i >= npts) return;
    const float* xp = x + (size_t)i * 3;
    atomicAdd(&g_hist[cell_of(xp[0], xp[1], xp[2])], 1u);
}

// scan stage 1: 1024 blocks x 256 threads; block b sums buckets [b*256, b*256+256)
__global__ void scan1_kernel()
{
    __shared__ unsigned int sm[256];
    int b = blockIdx.x, tid = threadIdx.x;
    sm[tid] = g_hist[b * CPER + tid];
    __syncthreads();
    for (int off = 128; off > 0; off >>= 1) {
        if (tid < off) sm[tid] += sm[tid + off];
        __syncthreads();
    }
    if (tid == 0) g_part[b] = sm[0];
}

// scan stage 2: single block scans the 1024 partials -> exclusive
__global__ void scan2_kernel()
{
    __shared__ unsigned int sm[NCHUNK];
    int tid = threadIdx.x;
    sm[tid] = g_part[tid];
    __syncthreads();
    for (int off = 1; off < NCHUNK; off <<= 1) {
        unsigned v = (tid >= off) ? sm[tid - off] : 0u;
        __syncthreads();
        sm[tid] += v;
        __syncthreads();
    }
    g_pexc[tid] = sm[tid] - g_part[tid];   // exclusive
}

// scan stage 3: 1024 blocks x 256 threads; block-local exclusive scan + chunk base
__global__ void scan3_kernel()
{
    __shared__ unsigned int sm[256];
    int b = blockIdx.x, tid = threadIdx.x;
    unsigned v = g_hist[b * CPER + tid];
    sm[tid] = v;
    __syncthreads();
    for (int off = 1; off < 256; off <<= 1) {
        unsigned u = (tid >= off) ? sm[tid - off] : 0u;
        __syncthreads();
        sm[tid] += u;
        __syncthreads();
    }
    g_offs[b * CPER + tid] = sm[tid] - v + g_pexc[b];
}

__global__ void scatter_kernel(const float* __restrict__ x, int npts)
{
    int i = blockIdx.x * blockDim.x + threadIdx.x;
    if (i >= npts) return;
    const float* xp = x + (size_t)i * 3;
    float px = xp[0], py = xp[1], pz = xp[2];
    unsigned cell = cell_of(px, py, pz);
    unsigned pos = atomicAdd(&g_offs[cell], 1u);
    if (pos < CAPP) g_pts[pos] = make_float4(px, py, pz, __uint_as_float((unsigned)i));
}

// ---------------- encode kernel ----------------

__global__ __launch_bounds__(256)
void ngp_encode_sorted_kernel(const float* __restrict__ tables,
                              float* __restrict__ out,
                              int npts)
{
    // block = 256 threads = 8 warps = 4 warp-pairs = 16 points.
    // warp: lane>>3 = point slot (0..3), level = ((wid&1)<<3) | (lane&7).
    int tid  = threadIdx.x;
    int wid  = tid >> 5;
    int lane = tid & 31;
    int pslot = lane >> 3;
    int level = ((wid & 1) << 3) | (lane & 7);
    int sp = blockIdx.x * 16 + (wid >> 1) * 4 + pslot;
    if (sp >= npts) return;

    float4 pt = g_pts[sp];
    float px = pt.x, py = pt.y, pz = pt.z;
    int point = (int)__float_as_uint(pt.w);

    float res = __ldg(g_res + level);

    // ---- grid coords + fracs (fp32, matches jnp) ----
    float sx = px * res, sy = py * res, sz = pz * res;
    float fx_ = floorf(sx), fy_ = floorf(sy), fz_ = floorf(sz);
    float gx = sx - fx_, gy = sy - fy_, gz = sz - fz_;
    uint32_t ix = (uint32_t)fx_, iy = (uint32_t)fy_, iz = (uint32_t)fz_;

    uint32_t hy0 = iy * NGP_P1;
    uint32_t hy1 = hy0 + NGP_P1;
    uint32_t hz0 = iz * NGP_P2;
    uint32_t hz1 = hz0 + NGP_P2;

    uint32_t m00 = hy0 ^ hz0;
    uint32_t m01 = hy0 ^ hz1;
    uint32_t m10 = hy1 ^ hz0;
    uint32_t m11 = hy1 ^ hz1;

    const float2* tbl = (const float2*)tables + (size_t)level * NGP_T;

    float wx0 = 1.f - gx, wx1 = gx;
    float wy0 = 1.f - gy, wy1 = gy;
    float wz0 = 1.f - gz, wz1 = gz;

    float w00 = wy0 * wz0;
    float w01 = wy0 * wz1;
    float w10 = wy1 * wz0;
    float w11 = wy1 * wz1;

    float ax = 0.f, ay = 0.f;

    if ((ix & 1u) == 0u) {
        uint32_t a00 = (ix ^ m00) & NGP_TMASK;
        uint32_t a01 = (ix ^ m01) & NGP_TMASK;
        uint32_t a10 = (ix ^ m10) & NGP_TMASK;
        uint32_t a11 = (ix ^ m11) & NGP_TMASK;

        const float4* t4 = (const float4*)tbl;
        float4 q00 = __ldg(t4 + (a00 >> 1));
        float4 q01 = __ldg(t4 + (a01 >> 1));
        float4 q10 = __ldg(t4 + (a10 >> 1));
        float4 q11 = __ldg(t4 + (a11 >> 1));

        float wl00 = (a00 & 1u) ? wx1 : wx0;  float wh00 = (a00 & 1u) ? wx0 : wx1;
        float wl01 = (a01 & 1u) ? wx1 : wx0;  float wh01 = (a01 & 1u) ? wx0 : wx1;
        float wl10 = (a10 & 1u) ? wx1 : wx0;  float wh10 = (a10 & 1u) ? wx0 : wx1;
        float wl11 = (a11 & 1u) ? wx1 : wx0;  float wh11 = (a11 & 1u) ? wx0 : wx1;

        ax = fmaf(w00, fmaf(wl00, q00.x, wh00 * q00.z), ax);
        ay = fmaf(w00, fmaf(wl00, q00.y, wh00 * q00.w), ay);
        ax = fmaf(w01, fmaf(wl01, q01.x, wh01 * q01.z), ax);
        ay = fmaf(w01, fmaf(wl01, q01.y, wh01 * q01.w), ay);
        ax = fmaf(w10, fmaf(wl10, q10.x, wh10 * q10.z), ax);
        ay = fmaf(w10, fmaf(wl10, q10.y, wh10 * q10.w), ay);
        ax = fmaf(w11, fmaf(wl11, q11.x, wh11 * q11.z), ax);
        ay = fmaf(w11, fmaf(wl11, q11.y, wh11 * q11.w), ay);
    } else {
        uint32_t ix1 = ix + 1u;
        uint32_t a0 = (ix  ^ m00) & NGP_TMASK;
        uint32_t a1 = (ix  ^ m01) & NGP_TMASK;
        uint32_t a2 = (ix  ^ m10) & NGP_TMASK;
        uint32_t a3 = (ix  ^ m11) & NGP_TMASK;
        uint32_t a4 = (ix1 ^ m00) & NGP_TMASK;
        uint32_t a5 = (ix1 ^ m01) & NGP_TMASK;
        uint32_t a6 = (ix1 ^ m10) & NGP_TMASK;
        uint32_t a7 = (ix1 ^ m11) & NGP_TMASK;

        float2 fA00 = __ldg(tbl + a0);
        float2 fA01 = __ldg(tbl + a1);
        float2 fA10 = __ldg(tbl + a2);
        float2 fA11 = __ldg(tbl + a3);
        float2 fB00 = __ldg(tbl + a4);
        float2 fB01 = __ldg(tbl + a5);
        float2 fB10 = __ldg(tbl + a6);
        float2 fB11 = __ldg(tbl + a7);

        ax = fmaf(w00, fmaf(wx0, fA00.x, wx1 * fB00.x), ax);
        ay = fmaf(w00, fmaf(wx0, fA00.y, wx1 * fB00.y), ay);
        ax = fmaf(w01, fmaf(wx0, fA01.x, wx1 * fB01.x), ax);
        ay = fmaf(w01, fmaf(wx0, fA01.y, wx1 * fB01.y), ay);
        ax = fmaf(w10, fmaf(wx0, fA10.x, wx1 * fB10.x), ax);
        ay = fmaf(w10, fmaf(wx0, fA10.y, wx1 * fB10.y), ay);
        ax = fmaf(w11, fmaf(wx0, fA11.x, wx1 * fB11.x), ax);
        ay = fmaf(w11, fmaf(wx0, fA11.y, wx1 * fB11.y), ay);
    }

    float2* op = (float2*)out + (size_t)point * NGP_LEVELS + level;
    *op = make_float2(ax, ay);
}

// ---------------- launch ----------------

extern "C" void kernel_launch(void* const* d_in, const int* in_sizes, int n_in,
                              void* d_out, int out_size)
{
    const float* x      = (const float*)d_in[0];   // [N,3]
    const float* tables = (const float*)d_in[1];   // [16, 2^19, 2]
    float* out          = (float*)d_out;           // [N,32]

    int npts = in_sizes[0] / 3;

    zero_hist_kernel<<<(NB3 + 255) / 256, 256>>>();
    hist_kernel<<<(npts + 255) / 256, 256>>>(x, npts);
    scan1_kernel<<<NCHUNK, CPER>>>();
    scan2_kernel<<<1, NCHUNK>>>();
    scan3_kernel<<<NCHUNK, CPER>>>();
    scatter_kernel<<<(npts + 255) / 256, 256>>>(x, npts);

    int nblocks = (npts + 15) / 16;
    ngp_encode_sorted_kernel<<<nblocks, 256>>>(tables, out, npts);
}

// round 9
// speedup vs baseline: 2.9192x; 1.0074x over previous
#include <cuda_runtime.h>
#include <stdint.h>

// Instant-NGP hash-grid encode with spatial bucketing.
// Pipeline (5 prelude kernels + encode):
//   zero-hist -> hist -> scan1 (chunk sums) -> scan23 (per-chunk prefix by
//   reduction + local scan) -> scatter -> encode.
// Encode: warp = 4 sorted points x 8 levels (thread = 1 level); sorted
// neighbors share corner cache lines at coarse levels. Even-ix corner pairs
// load as one aligned float4 (hash x-prime = 1).

#define NGP_LEVELS 16
#define NGP_T      524288u
#define NGP_TMASK  (NGP_T - 1u)
#define NGP_P1     2654435761u
#define NGP_P2     805459861u

#define NB   64
#define NB3  (NB*NB*NB)            // 262144 buckets
#define NCHUNK 1024                 // scan chunks
#define CPER  (NB3/NCHUNK)          // 256 buckets per chunk
#define CAPP (1u<<21)

__device__ unsigned int g_hist[NB3];
__device__ unsigned int g_offs[NB3];
__device__ unsigned int g_part[NCHUNK];
__device__ float4       g_pts[CAPP];     // sorted (x,y,z,bitcast(point))

__device__ float g_res[NGP_LEVELS] = {
    16.f, 24.f, 36.f, 54.f, 81.f, 121.f, 182.f, 273.f,
    410.f, 615.f, 922.f, 1383.f, 2075.f, 3113.f, 4670.f, 7006.f
};

// ---------------- sort kernels ----------------

__global__ void zero_hist_kernel()
{
    int i = blockIdx.x * blockDim.x + threadIdx.x;
    if (i < NB3) g_hist[i] = 0u;
}

__device__ __forceinline__ unsigned int cell_of(float px, float py, float pz)
{
    unsigned cx = (unsigned)fminf(fmaxf(px * (float)NB, 0.f), (float)(NB - 1));
    unsigned cy = (unsigned)fminf(fmaxf(py * (float)NB, 0.f), (float)(NB - 1));
    unsigned cz = (unsigned)fminf(fmaxf(pz * (float)NB, 0.f), (float)(NB - 1));
    return (cz * NB + cy) * NB + cx;
}

__global__ void hist_kernel(const float* __restrict__ x, int npts)
{
    int i = blockIdx.x * blockDim.x + threadIdx.x;
    if (i >= npts) return;
    const float* xp = x + (size_t)i * 3;
    atomicAdd(&g_hist[cell_of(xp[0], xp[1], xp[2])], 1u);
}

// stage 1: 1024 blocks x 256 threads; block b sums buckets [b*256, (b+1)*256)
__global__ void scan1_kernel()
{
    __shared__ unsigned int sm[CPER];
    int b = blockIdx.x, tid = threadIdx.x;
    sm[tid] = g_hist[b * CPER + tid];
    __syncthreads();
    for (int off = 128; off > 0; off >>= 1) {
        if (tid < off) sm[tid] += sm[tid + off];
        __syncthreads();
    }
    if (tid == 0) g_part[b] = sm[0];
}

// stage 2+3 fused: block b computes its own prefix (reduction over
// g_part[0..b-1]) then the local exclusive scan of its 256 buckets.
__global__ void scan23_kernel()
{
    __shared__ unsigned int red[CPER];
    __shared__ unsigned int sm[CPER];
    int b = blockIdx.x, tid = threadIdx.x;

    // chunk base = sum of partials of all preceding chunks
    unsigned s = 0;
    for (int i = tid; i < b; i += CPER) s += g_part[i];
    red[tid] = s;
    __syncthreads();
    for (int off = 128; off > 0; off >>= 1) {
        if (tid < off) red[tid] += red[tid + off];
        __syncthreads();
    }
    unsigned base = red[0];

    // local exclusive scan of this chunk's buckets
    unsigned v = g_hist[b * CPER + tid];
    sm[tid] = v;
    __syncthreads();
    for (int off = 1; off < CPER; off <<= 1) {
        unsigned u = (tid >= off) ? sm[tid - off] : 0u;
        __syncthreads();
        sm[tid] += u;
        __syncthreads();
    }
    g_offs[b * CPER + tid] = sm[tid] - v + base;
}

__global__ void scatter_kernel(const float* __restrict__ x, int npts)
{
    int i = blockIdx.x * blockDim.x + threadIdx.x;
    if (i >= npts) return;
    const float* xp = x + (size_t)i * 3;
    float px = xp[0], py = xp[1], pz = xp[2];
    unsigned cell = cell_of(px, py, pz);
    unsigned pos = atomicAdd(&g_offs[cell], 1u);
    if (pos < CAPP) g_pts[pos] = make_float4(px, py, pz, __uint_as_float((unsigned)i));
}

// ---------------- encode kernel ----------------

__global__ __launch_bounds__(256)
void ngp_encode_sorted_kernel(const float* __restrict__ tables,
                              float* __restrict__ out,
                              int npts)
{
    // block = 256 threads = 8 warps = 16 points.
    // warp: lane>>3 = point slot (0..3), level = ((wid&1)<<3) | (lane&7).
    int tid  = threadIdx.x;
    int wid  = tid >> 5;
    int lane = tid & 31;
    int pslot = lane >> 3;
    int level = ((wid & 1) << 3) | (lane & 7);
    int sp = blockIdx.x * 16 + (wid >> 1) * 4 + pslot;
    if (sp >= npts) return;

    float4 pt = g_pts[sp];
    float px = pt.x, py = pt.y, pz = pt.z;
    int point = (int)__float_as_uint(pt.w);

    float res = __ldg(g_res + level);

    // ---- grid coords + fracs (fp32, matches jnp) ----
    float sx = px * res, sy = py * res, sz = pz * res;
    float fx_ = floorf(sx), fy_ = floorf(sy), fz_ = floorf(sz);
    float gx = sx - fx_, gy = sy - fy_, gz = sz - fz_;
    uint32_t ix = (uint32_t)fx_, iy = (uint32_t)fy_, iz = (uint32_t)fz_;

    uint32_t hy0 = iy * NGP_P1;
    uint32_t hy1 = hy0 + NGP_P1;
    uint32_t hz0 = iz * NGP_P2;
    uint32_t hz1 = hz0 + NGP_P2;

    uint32_t m00 = hy0 ^ hz0;
    uint32_t m01 = hy0 ^ hz1;
    uint32_t m10 = hy1 ^ hz0;
    uint32_t m11 = hy1 ^ hz1;

    const float2* tbl = (const float2*)tables + (size_t)level * NGP_T;

    float wx0 = 1.f - gx, wx1 = gx;
    float wy0 = 1.f - gy, wy1 = gy;
    float wz0 = 1.f - gz, wz1 = gz;

    float w00 = wy0 * wz0;
    float w01 = wy0 * wz1;
    float w10 = wy1 * wz0;
    float w11 = wy1 * wz1;

    float ax = 0.f, ay = 0.f;

    if ((ix & 1u) == 0u) {
        uint32_t a00 = (ix ^ m00) & NGP_TMASK;
        uint32_t a01 = (ix ^ m01) & NGP_TMASK;
        uint32_t a10 = (ix ^ m10) & NGP_TMASK;
        uint32_t a11 = (ix ^ m11) & NGP_TMASK;

        const float4* t4 = (const float4*)tbl;
        float4 q00 = __ldg(t4 + (a00 >> 1));
        float4 q01 = __ldg(t4 + (a01 >> 1));
        float4 q10 = __ldg(t4 + (a10 >> 1));
        float4 q11 = __ldg(t4 + (a11 >> 1));

        float wl00 = (a00 & 1u) ? wx1 : wx0;  float wh00 = (a00 & 1u) ? wx0 : wx1;
        float wl01 = (a01 & 1u) ? wx1 : wx0;  float wh01 = (a01 & 1u) ? wx0 : wx1;
        float wl10 = (a10 & 1u) ? wx1 : wx0;  float wh10 = (a10 & 1u) ? wx0 : wx1;
        float wl11 = (a11 & 1u) ? wx1 : wx0;  float wh11 = (a11 & 1u) ? wx0 : wx1;

        ax = fmaf(w00, fmaf(wl00, q00.x, wh00 * q00.z), ax);
        ay = fmaf(w00, fmaf(wl00, q00.y, wh00 * q00.w), ay);
        ax = fmaf(w01, fmaf(wl01, q01.x, wh01 * q01.z), ax);
        ay = fmaf(w01, fmaf(wl01, q01.y, wh01 * q01.w), ay);
        ax = fmaf(w10, fmaf(wl10, q10.x, wh10 * q10.z), ax);
        ay = fmaf(w10, fmaf(wl10, q10.y, wh10 * q10.w), ay);
        ax = fmaf(w11, fmaf(wl11, q11.x, wh11 * q11.z), ax);
        ay = fmaf(w11, fmaf(wl11, q11.y, wh11 * q11.w), ay);
    } else {
        uint32_t ix1 = ix + 1u;
        uint32_t a0 = (ix  ^ m00) & NGP_TMASK;
        uint32_t a1 = (ix  ^ m01) & NGP_TMASK;
        uint32_t a2 = (ix  ^ m10) & NGP_TMASK;
        uint32_t a3 = (ix  ^ m11) & NGP_TMASK;
        uint32_t a4 = (ix1 ^ m00) & NGP_TMASK;
        uint32_t a5 = (ix1 ^ m01) & NGP_TMASK;
        uint32_t a6 = (ix1 ^ m10) & NGP_TMASK;
        uint32_t a7 = (ix1 ^ m11) & NGP_TMASK;

        float2 fA00 = __ldg(tbl + a0);
        float2 fA01 = __ldg(tbl + a1);
        float2 fA10 = __ldg(tbl + a2);
        float2 fA11 = __ldg(tbl + a3);
        float2 fB00 = __ldg(tbl + a4);
        float2 fB01 = __ldg(tbl + a5);
        float2 fB10 = __ldg(tbl + a6);
        float2 fB11 = __ldg(tbl + a7);

        ax = fmaf(w00, fmaf(wx0, fA00.x, wx1 * fB00.x), ax);
        ay = fmaf(w00, fmaf(wx0, fA00.y, wx1 * fB00.y), ay);
        ax = fmaf(w01, fmaf(wx0, fA01.x, wx1 * fB01.x), ax);
        ay = fmaf(w01, fmaf(wx0, fA01.y, wx1 * fB01.y), ay);
        ax = fmaf(w10, fmaf(wx0, fA10.x, wx1 * fB10.x), ax);
        ay = fmaf(w10, fmaf(wx0, fA10.y, wx1 * fB10.y), ay);
        ax = fmaf(w11, fmaf(wx0, fA11.x, wx1 * fB11.x), ax);
        ay = fmaf(w11, fmaf(wx0, fA11.y, wx1 * fB11.y), ay);
    }

    float2* op = (float2*)out + (size_t)point * NGP_LEVELS + level;
    *op = make_float2(ax, ay);
}

// ---------------- launch ----------------

extern "C" void kernel_launch(void* const* d_in, const int* in_sizes, int n_in,
                              void* d_out, int out_size)
{
    const float* x      = (const float*)d_in[0];   // [N,3]
    const float* tables = (const float*)d_in[1];   // [16, 2^19, 2]
    float* out          = (float*)d_out;           // [N,32]

    int npts = in_sizes[0] / 3;

    zero_hist_kernel<<<(NB3 + 255) / 256, 256>>>();
    hist_kernel<<<(npts + 255) / 256, 256>>>(x, npts);
    scan1_kernel<<<NCHUNK, CPER>>>();
    scan23_kernel<<<NCHUNK, CPER>>>();
    scatter_kernel<<<(npts + 255) / 256, 256>>>(x, npts);

    int nblocks = (npts + 15) / 16;
    ngp_encode_sorted_kernel<<<nblocks, 256>>>(tables, out, npts);
}